// round 1
// baseline (speedup 1.0000x reference)
#include <cuda_runtime.h>
#include <cstdint>

#define NUM_USER     200000
#define NUM_QUESTION 20000
#define NC           128
#define DH           512
#define H2           256
#define BATCH        16384
#define MAXE         384

// ---------------- scratch (__device__ globals: no allocation allowed) ----------------
__device__ float g_SP [BATCH * NC];    // sigmoid(priori[user]) gathered per row
__device__ float g_SCP[BATCH * MAXE];  // sigmoid(condi_p)^(1/lp) per edge
__device__ float g_SCN[BATCH * MAXE];  // sigmoid(condi_n)^(1/lp) per edge
__device__ float g_Bm [BATCH * NC];    // sigmoid(item_diff[q]) * q_table[q]
__device__ float g_Disc[BATCH];        // sigmoid(item_disc[q])
__device__ float g_A  [BATCH * NC];    // mastery * q_table[q]
__device__ float g_X  [BATCH * DH];    // (user_factor - item_factor)*disc
__device__ float g_H  [BATCH * H2];    // hidden layer

struct EdgeExp { unsigned char lp[MAXE]; };              // lp of the concept owning edge j
struct GraphP  { unsigned char lp[NC]; unsigned char pred[NC][3]; };

__device__ __forceinline__ float sigmoidf(float x) {
    return __fdividef(1.0f, 1.0f + __expf(-x));
}

// ---------------- K0: elementwise transforms (fully parallel) ----------------
__global__ void k_elem(const int* __restrict__ uid, const int* __restrict__ qid,
                       const float* __restrict__ priori,
                       const float* __restrict__ condi_p, const float* __restrict__ condi_n,
                       const float* __restrict__ idiff, const float* __restrict__ idisc,
                       const float* __restrict__ qt,
                       EdgeExp ee, int E)
{
    int b   = blockIdx.y;
    int idx = blockIdx.x * blockDim.x + threadIdx.x;
    int total = 2 * NC + 2 * E + 1;
    if (idx >= total) return;
    if (idx < NC) {
        int u = uid[b];
        g_SP[b * NC + idx] = sigmoidf(priori[(size_t)u * NC + idx]);
    } else if (idx < NC + 2 * E) {
        int u = uid[b];
        int j = idx - NC;
        bool isP = (j < E);
        if (!isP) j -= E;
        const float* src = isP ? condi_p : condi_n;
        float v = sigmoidf(src[(size_t)u * E + j]);
        int l = ee.lp[j];
        if (l == 2)      v = sqrtf(v);
        else if (l == 3) v = __powf(v, 0.33333334f);
        float* dst = isP ? g_SCP : g_SCN;
        dst[(size_t)b * E + j] = v;
    } else if (idx < 2 * NC + 2 * E) {
        int q = qid[b];
        int k = idx - NC - 2 * E;
        g_Bm[b * NC + k] = sigmoidf(idiff[(size_t)q * NC + k]) * qt[(size_t)q * NC + k];
    } else {
        int q = qid[b];
        g_Disc[b] = sigmoidf(idisc[q]);
    }
}

// ---------------- K1: sequential posterior chain (one thread per row) ----------------
__global__ void k_mastery(const int* __restrict__ qid, const float* __restrict__ qt,
                          GraphP g, int E)
{
    int b = blockIdx.x * blockDim.x + threadIdx.x;
    if (b >= BATCH) return;
    const float* sp  = g_SP  + b * NC;
    const float* scp = g_SCP + (size_t)b * E;
    const float* scn = g_SCN + (size_t)b * E;
    float m[NC];
    int off = 0;
    #pragma unroll 1
    for (int k = 0; k < NC; k++) {
        int l = g.lp[k];
        float v;
        if (l == 0) {
            v = sp[k];
        } else {
            v = 1.0f;
            #pragma unroll 1
            for (int j = 0; j < l; j++) {
                float mp = m[g.pred[k][j]];
                v *= scp[off + j] * mp + scn[off + j] * (1.0f - mp);
            }
            off += l;
        }
        m[k] = v;
    }
    int q = qid[b];
    const float* qr = qt + (size_t)q * NC;
    float* a = g_A + b * NC;
    #pragma unroll 4
    for (int k = 0; k < NC; k++) a[k] = m[k] * qr[k];
}

// ---------------- K2: fused GEMMs U/I + factor epilogue -> X ----------------
// X[m,n] = (tanh(A@Wu^T + bu) - sigmoid(Bm@Wi^T + bi)) * disc
// Tile: 128(M) x 64(N), BK=16, 256 threads, 8x4 register tile.
__global__ void __launch_bounds__(256) k_factor(const float* __restrict__ Wu,
                                                const float* __restrict__ bu,
                                                const float* __restrict__ Wi,
                                                const float* __restrict__ bi)
{
    __shared__ float sA [128][17];
    __shared__ float sB [128][17];
    __shared__ float sWu[64][17];
    __shared__ float sWi[64][17];
    int m0 = blockIdx.x * 128;
    int n0 = blockIdx.y * 64;
    int t = threadIdx.x, tx = t & 15, ty = t >> 4;
    float accU[8][4], accI[8][4];
    #pragma unroll
    for (int i = 0; i < 8; i++)
        #pragma unroll
        for (int j = 0; j < 4; j++) { accU[i][j] = 0.f; accI[i][j] = 0.f; }

    for (int kc = 0; kc < NC; kc += 16) {
        #pragma unroll
        for (int i = 0; i < 2; i++) {
            int f4 = t + i * 256;
            int r = f4 >> 2, c = (f4 & 3) * 4;
            float4 va = *(const float4*)(g_A  + (size_t)(m0 + r) * NC + kc + c);
            sA[r][c] = va.x; sA[r][c+1] = va.y; sA[r][c+2] = va.z; sA[r][c+3] = va.w;
            float4 vb = *(const float4*)(g_Bm + (size_t)(m0 + r) * NC + kc + c);
            sB[r][c] = vb.x; sB[r][c+1] = vb.y; sB[r][c+2] = vb.z; sB[r][c+3] = vb.w;
        }
        {
            int r = t >> 2, c = (t & 3) * 4;
            float4 vu = *(const float4*)(Wu + (size_t)(n0 + r) * NC + kc + c);
            sWu[r][c] = vu.x; sWu[r][c+1] = vu.y; sWu[r][c+2] = vu.z; sWu[r][c+3] = vu.w;
            float4 vi = *(const float4*)(Wi + (size_t)(n0 + r) * NC + kc + c);
            sWi[r][c] = vi.x; sWi[r][c+1] = vi.y; sWi[r][c+2] = vi.z; sWi[r][c+3] = vi.w;
        }
        __syncthreads();
        #pragma unroll
        for (int kk = 0; kk < 16; kk++) {
            float a[8], b_[8], wu[4], wi[4];
            #pragma unroll
            for (int i = 0; i < 8; i++) { a[i] = sA[ty*8+i][kk]; b_[i] = sB[ty*8+i][kk]; }
            #pragma unroll
            for (int j = 0; j < 4; j++) { wu[j] = sWu[tx*4+j][kk]; wi[j] = sWi[tx*4+j][kk]; }
            #pragma unroll
            for (int i = 0; i < 8; i++)
                #pragma unroll
                for (int j = 0; j < 4; j++) {
                    accU[i][j] += a[i]  * wu[j];
                    accI[i][j] += b_[i] * wi[j];
                }
        }
        __syncthreads();
    }
    float bus[4], bis[4];
    #pragma unroll
    for (int j = 0; j < 4; j++) { bus[j] = bu[n0 + tx*4 + j]; bis[j] = bi[n0 + tx*4 + j]; }
    #pragma unroll
    for (int i = 0; i < 8; i++) {
        int row = m0 + ty * 8 + i;
        float d = g_Disc[row];
        float4 o;
        float u0 = tanhf(accU[i][0] + bus[0]);
        float u1 = tanhf(accU[i][1] + bus[1]);
        float u2 = tanhf(accU[i][2] + bus[2]);
        float u3 = tanhf(accU[i][3] + bus[3]);
        o.x = (u0 - sigmoidf(accI[i][0] + bis[0])) * d;
        o.y = (u1 - sigmoidf(accI[i][1] + bis[1])) * d;
        o.z = (u2 - sigmoidf(accI[i][2] + bis[2])) * d;
        o.w = (u3 - sigmoidf(accI[i][3] + bis[3])) * d;
        *(float4*)(g_X + (size_t)row * DH + n0 + tx * 4) = o;
    }
}

// ---------------- K3: GEMM H = sigmoid(X@W1^T + b1) ----------------
__global__ void __launch_bounds__(256) k_mlp1(const float* __restrict__ W1,
                                              const float* __restrict__ b1)
{
    __shared__ float sX[128][17];
    __shared__ float sW[64][17];
    int m0 = blockIdx.x * 128;
    int n0 = blockIdx.y * 64;
    int t = threadIdx.x, tx = t & 15, ty = t >> 4;
    float acc[8][4];
    #pragma unroll
    for (int i = 0; i < 8; i++)
        #pragma unroll
        for (int j = 0; j < 4; j++) acc[i][j] = 0.f;

    for (int kc = 0; kc < DH; kc += 16) {
        #pragma unroll
        for (int i = 0; i < 2; i++) {
            int f4 = t + i * 256;
            int r = f4 >> 2, c = (f4 & 3) * 4;
            float4 v = *(const float4*)(g_X + (size_t)(m0 + r) * DH + kc + c);
            sX[r][c] = v.x; sX[r][c+1] = v.y; sX[r][c+2] = v.z; sX[r][c+3] = v.w;
        }
        {
            int r = t >> 2, c = (t & 3) * 4;
            float4 v = *(const float4*)(W1 + (size_t)(n0 + r) * DH + kc + c);
            sW[r][c] = v.x; sW[r][c+1] = v.y; sW[r][c+2] = v.z; sW[r][c+3] = v.w;
        }
        __syncthreads();
        #pragma unroll
        for (int kk = 0; kk < 16; kk++) {
            float a[8], w[4];
            #pragma unroll
            for (int i = 0; i < 8; i++) a[i] = sX[ty*8+i][kk];
            #pragma unroll
            for (int j = 0; j < 4; j++) w[j] = sW[tx*4+j][kk];
            #pragma unroll
            for (int i = 0; i < 8; i++)
                #pragma unroll
                for (int j = 0; j < 4; j++) acc[i][j] += a[i] * w[j];
        }
        __syncthreads();
    }
    float bs[4];
    #pragma unroll
    for (int j = 0; j < 4; j++) bs[j] = b1[n0 + tx*4 + j];
    #pragma unroll
    for (int i = 0; i < 8; i++) {
        int row = m0 + ty * 8 + i;
        float4 o;
        o.x = sigmoidf(acc[i][0] + bs[0]);
        o.y = sigmoidf(acc[i][1] + bs[1]);
        o.z = sigmoidf(acc[i][2] + bs[2]);
        o.w = sigmoidf(acc[i][3] + bs[3]);
        *(float4*)(g_H + (size_t)row * H2 + n0 + tx * 4) = o;
    }
}

// ---------------- K4: final GEMV + sigmoid ----------------
__global__ void k_out(const float* __restrict__ W2, const float* __restrict__ b2,
                      float* __restrict__ out)
{
    int gw   = (blockIdx.x * blockDim.x + threadIdx.x) >> 5;
    int lane = threadIdx.x & 31;
    if (gw >= BATCH) return;
    const float4* h4 = (const float4*)(g_H + (size_t)gw * H2);
    const float4* w4 = (const float4*)W2;
    float s = 0.f;
    #pragma unroll
    for (int i = 0; i < 2; i++) {
        float4 hv = h4[lane + i * 32], wv = w4[lane + i * 32];
        s += hv.x * wv.x + hv.y * wv.y + hv.z * wv.z + hv.w * wv.w;
    }
    #pragma unroll
    for (int o = 16; o; o >>= 1) s += __shfl_xor_sync(0xffffffffu, s, o);
    if (lane == 0) out[gw] = sigmoidf(s + b2[0]);
}

// ---------------- host: numpy-legacy MT19937 graph reconstruction ----------------
namespace {
struct MT { uint32_t mt[624]; int idx; };
static void mt_seed(MT& s, uint32_t seed) {
    s.mt[0] = seed;
    for (int i = 1; i < 624; i++)
        s.mt[i] = 1812433253u * (s.mt[i-1] ^ (s.mt[i-1] >> 30)) + (uint32_t)i;
    s.idx = 624;
}
static uint32_t mt_next(MT& s) {
    if (s.idx >= 624) {
        for (int i = 0; i < 624; i++) {
            uint32_t y = (s.mt[i] & 0x80000000u) | (s.mt[(i+1) % 624] & 0x7fffffffu);
            s.mt[i] = s.mt[(i+397) % 624] ^ (y >> 1) ^ ((y & 1u) ? 0x9908b0dfu : 0u);
        }
        s.idx = 0;
    }
    uint32_t y = s.mt[s.idx++];
    y ^= y >> 11;
    y ^= (y << 7)  & 0x9d2c5680u;
    y ^= (y << 15) & 0xefc60000u;
    y ^= y >> 18;
    return y;
}
// legacy randint(0, hi): masked rejection on 32-bit draws (rng = hi-1 <= 3 here)
static uint32_t draw_bounded(MT& s, uint32_t rng) {
    uint32_t mask = rng; mask |= mask >> 1; mask |= mask >> 2; mask |= mask >> 4;
    mask |= mask >> 8; mask |= mask >> 16;
    uint32_t v;
    do { v = mt_next(s) & mask; } while (v > rng);
    return v;
}
static void build_graph(GraphP& gp, EdgeExp& ee, int& E) {
    MT mt; mt_seed(mt, 0u);
    int off = 0;
    for (int k = 0; k < NC; k++) {
        int l = 0;
        if (k > 0) {
            int hi = (k < 3 ? k : 3) + 1;                 // randint(0, hi)
            l = (int)draw_bounded(mt, (uint32_t)(hi - 1));
        }
        int preds[3] = {0, 0, 0};
        if (l > 0) {
            int arr[NC];
            for (int i = 0; i < k; i++) arr[i] = i;
            for (int i = k - 1; i >= 1; i--) {            // legacy shuffle (Fisher-Yates)
                uint32_t j = draw_bounded(mt, (uint32_t)i); // random_interval(i)
                int tmp = arr[i]; arr[i] = arr[(int)j]; arr[(int)j] = tmp;
            }
            for (int jj = 0; jj < l; jj++) preds[jj] = arr[jj];
            // sort ascending (l <= 3)
            for (int a = 0; a < l; a++)
                for (int b2_ = a + 1; b2_ < l; b2_++)
                    if (preds[b2_] < preds[a]) { int tm = preds[a]; preds[a] = preds[b2_]; preds[b2_] = tm; }
        }
        gp.lp[k] = (unsigned char)l;
        for (int jj = 0; jj < 3; jj++) gp.pred[k][jj] = (unsigned char)(jj < l ? preds[jj] : 0);
        for (int jj = 0; jj < l; jj++) ee.lp[off + jj] = (unsigned char)l;
        off += l;
    }
    E = off;
}
} // namespace

extern "C" void kernel_launch(void* const* d_in, const int* in_sizes, int n_in,
                              void* d_out, int out_size)
{
    GraphP gp; EdgeExp ee; int E;
    build_graph(gp, ee, E);

    const int*   uid    = (const int*)  d_in[0];
    const int*   qid    = (const int*)  d_in[1];
    const float* priori = (const float*)d_in[2];
    const float* cpd    = (const float*)d_in[3];
    const float* cnd    = (const float*)d_in[4];
    const float* idiff  = (const float*)d_in[5];
    const float* idisc  = (const float*)d_in[6];
    const float* qt     = (const float*)d_in[7];
    const float* Wu     = (const float*)d_in[8];
    const float* bu     = (const float*)d_in[9];
    const float* Wi     = (const float*)d_in[10];
    const float* bi     = (const float*)d_in[11];
    const float* W1     = (const float*)d_in[12];
    const float* b1     = (const float*)d_in[13];
    const float* W2     = (const float*)d_in[14];
    const float* b2     = (const float*)d_in[15];
    float* out = (float*)d_out;

    // Prefer the harness-provided edge count if it disagrees (strides must match data).
    int Ein = in_sizes[3] / NUM_USER;
    if (Ein > 0 && Ein <= MAXE) E = Ein;

    int total = 2 * NC + 2 * E + 1;
    dim3 g0((total + 255) / 256, BATCH);
    k_elem<<<g0, 256>>>(uid, qid, priori, cpd, cnd, idiff, idisc, qt, ee, E);

    k_mastery<<<(BATCH + 127) / 128, 128>>>(qid, qt, gp, E);

    k_factor<<<dim3(BATCH / 128, DH / 64), 256>>>(Wu, bu, Wi, bi);

    k_mlp1<<<dim3(BATCH / 128, H2 / 64), 256>>>(W1, b1);

    k_out<<<(BATCH * 32 + 255) / 256, 256>>>(W2, b2, out);
}

// round 4
// speedup vs baseline: 1.5659x; 1.5659x over previous
#include <cuda_runtime.h>
#include <cstdint>

#define NUM_USER     200000
#define NUM_QUESTION 20000
#define NC           128
#define DH           512
#define H2           256
#define BATCH        16384
#define MAXE         384
#define LDS_         36   // smem row stride (floats): bank = 4*row+col, conflict-free frags

// ---------------- scratch (__device__ globals) ----------------
__device__ float g_SP [BATCH * NC];
__device__ float g_SCP[BATCH * MAXE];
__device__ float g_SCN[BATCH * MAXE];
__device__ float g_Bm [BATCH * NC];
__device__ float g_Disc[BATCH];
__device__ float g_A  [BATCH * NC];
__device__ float g_X  [BATCH * DH];
__device__ float g_H  [BATCH * H2];

struct EdgeExp { unsigned char lp[MAXE]; };
struct GraphP  { unsigned char lp[NC]; unsigned char pred[NC][3]; };

__device__ __forceinline__ float sigmoidf(float x) {
    return __fdividef(1.0f, 1.0f + __expf(-x));
}
__device__ __forceinline__ uint32_t f2tf(float f) {
    uint32_t r;
    asm("cvt.rna.tf32.f32 %0, %1;" : "=r"(r) : "f"(f));
    return r;
}
__device__ __forceinline__ void mma_tf32(float c[4],
                                         uint32_t a0, uint32_t a1, uint32_t a2, uint32_t a3,
                                         uint32_t b0, uint32_t b1) {
    asm volatile(
        "mma.sync.aligned.m16n8k8.row.col.f32.tf32.tf32.f32 "
        "{%0,%1,%2,%3}, {%4,%5,%6,%7}, {%8,%9}, {%0,%1,%2,%3};"
        : "+f"(c[0]), "+f"(c[1]), "+f"(c[2]), "+f"(c[3])
        : "r"(a0), "r"(a1), "r"(a2), "r"(a3), "r"(b0), "r"(b1));
}

// ---------------- K0: elementwise transforms ----------------
__global__ void k_elem(const int* __restrict__ uid, const int* __restrict__ qid,
                       const float* __restrict__ priori,
                       const float* __restrict__ condi_p, const float* __restrict__ condi_n,
                       const float* __restrict__ idiff, const float* __restrict__ idisc,
                       const float* __restrict__ qt,
                       EdgeExp ee, int E)
{
    int b   = blockIdx.y;
    int idx = blockIdx.x * blockDim.x + threadIdx.x;
    int total = 2 * NC + 2 * E + 1;
    if (idx >= total) return;
    if (idx < NC) {
        int u = uid[b];
        g_SP[b * NC + idx] = sigmoidf(priori[(size_t)u * NC + idx]);
    } else if (idx < NC + 2 * E) {
        int u = uid[b];
        int j = idx - NC;
        bool isP = (j < E);
        if (!isP) j -= E;
        const float* src = isP ? condi_p : condi_n;
        float v = sigmoidf(src[(size_t)u * E + j]);
        int l = ee.lp[j];
        if (l == 2)      v = sqrtf(v);
        else if (l == 3) v = __powf(v, 0.33333334f);
        float* dst = isP ? g_SCP : g_SCN;
        dst[(size_t)b * E + j] = v;
    } else if (idx < 2 * NC + 2 * E) {
        int q = qid[b];
        int k = idx - NC - 2 * E;
        g_Bm[b * NC + k] = sigmoidf(idiff[(size_t)q * NC + k]) * qt[(size_t)q * NC + k];
    } else {
        int q = qid[b];
        g_Disc[b] = sigmoidf(idisc[q]);
    }
}

// ---------------- K1: sequential posterior chain ----------------
__global__ void k_mastery(const int* __restrict__ qid, const float* __restrict__ qt,
                          GraphP g, int E)
{
    int b = blockIdx.x * blockDim.x + threadIdx.x;
    if (b >= BATCH) return;
    const float* sp  = g_SP  + b * NC;
    const float* scp = g_SCP + (size_t)b * E;
    const float* scn = g_SCN + (size_t)b * E;
    float m[NC];
    int off = 0;
    #pragma unroll 1
    for (int k = 0; k < NC; k++) {
        int l = g.lp[k];
        float v;
        if (l == 0) {
            v = sp[k];
        } else {
            v = 1.0f;
            #pragma unroll 1
            for (int j = 0; j < l; j++) {
                float mp = m[g.pred[k][j]];
                v *= scp[off + j] * mp + scn[off + j] * (1.0f - mp);
            }
            off += l;
        }
        m[k] = v;
    }
    int q = qid[b];
    const float* qr = qt + (size_t)q * NC;
    float* a = g_A + b * NC;
    #pragma unroll 4
    for (int k = 0; k < NC; k++) a[k] = m[k] * qr[k];
}

// ---------------- K2: dual tf32-MMA GEMM + factor epilogue ----------------
// g_X[m,n] = (tanh((g_A@Wu^T)[m,n] + bu[n]) - sigmoid((g_Bm@Wi^T)[m,n] + bi[n])) * disc[m]
// CTA 128x128, BK=32. 8 warps: 2(M) x 4(N). Warp tile 64x32 -> 4x4 m16n8k8 frags.
__global__ void __launch_bounds__(256) k_factor_mma(const float* __restrict__ Wu,
                                                    const float* __restrict__ bu,
                                                    const float* __restrict__ Wi,
                                                    const float* __restrict__ bi)
{
    extern __shared__ uint32_t smx[];
    uint32_t* sA  = smx;
    uint32_t* sBm = smx + 128 * LDS_;
    uint32_t* sWu = smx + 2 * 128 * LDS_;
    uint32_t* sWi = smx + 3 * 128 * LDS_;

    int t = threadIdx.x, lane = t & 31, warp = t >> 5;
    int wm = (warp & 1) * 64;
    int wn = (warp >> 1) * 32;
    int m0 = blockIdx.x * 128, n0 = blockIdx.y * 128;
    int g   = lane >> 2;   // group id
    int tig = lane & 3;    // thread-in-group

    float cU[4][4][4], cI[4][4][4];
    #pragma unroll
    for (int mi = 0; mi < 4; mi++)
        #pragma unroll
        for (int ni = 0; ni < 4; ni++)
            #pragma unroll
            for (int q = 0; q < 4; q++) { cU[mi][ni][q] = 0.f; cI[mi][ni][q] = 0.f; }

    for (int kt = 0; kt < NC; kt += 32) {
        #pragma unroll
        for (int i = 0; i < 4; i++) {
            int idx = t + i * 256;
            int r = idx >> 3, c = (idx & 7) * 4;
            float4 v;
            v = *(const float4*)(g_A  + (size_t)(m0 + r) * NC + kt + c);
            sA [r * LDS_ + c] = f2tf(v.x); sA [r * LDS_ + c + 1] = f2tf(v.y);
            sA [r * LDS_ + c + 2] = f2tf(v.z); sA [r * LDS_ + c + 3] = f2tf(v.w);
            v = *(const float4*)(g_Bm + (size_t)(m0 + r) * NC + kt + c);
            sBm[r * LDS_ + c] = f2tf(v.x); sBm[r * LDS_ + c + 1] = f2tf(v.y);
            sBm[r * LDS_ + c + 2] = f2tf(v.z); sBm[r * LDS_ + c + 3] = f2tf(v.w);
            v = *(const float4*)(Wu + (size_t)(n0 + r) * NC + kt + c);
            sWu[r * LDS_ + c] = f2tf(v.x); sWu[r * LDS_ + c + 1] = f2tf(v.y);
            sWu[r * LDS_ + c + 2] = f2tf(v.z); sWu[r * LDS_ + c + 3] = f2tf(v.w);
            v = *(const float4*)(Wi + (size_t)(n0 + r) * NC + kt + c);
            sWi[r * LDS_ + c] = f2tf(v.x); sWi[r * LDS_ + c + 1] = f2tf(v.y);
            sWi[r * LDS_ + c + 2] = f2tf(v.z); sWi[r * LDS_ + c + 3] = f2tf(v.w);
        }
        __syncthreads();
        #pragma unroll
        for (int kk = 0; kk < 4; kk++) {
            int kb = kk * 8;
            uint32_t bfu[4][2], bfi[4][2];
            #pragma unroll
            for (int ni = 0; ni < 4; ni++) {
                int n = wn + ni * 8 + g;
                bfu[ni][0] = sWu[n * LDS_ + kb + tig];
                bfu[ni][1] = sWu[n * LDS_ + kb + tig + 4];
                bfi[ni][0] = sWi[n * LDS_ + kb + tig];
                bfi[ni][1] = sWi[n * LDS_ + kb + tig + 4];
            }
            #pragma unroll
            for (int mi = 0; mi < 4; mi++) {
                int r = wm + mi * 16 + g;
                uint32_t aA0 = sA [r * LDS_ + kb + tig];
                uint32_t aA1 = sA [(r + 8) * LDS_ + kb + tig];
                uint32_t aA2 = sA [r * LDS_ + kb + tig + 4];
                uint32_t aA3 = sA [(r + 8) * LDS_ + kb + tig + 4];
                uint32_t aB0 = sBm[r * LDS_ + kb + tig];
                uint32_t aB1 = sBm[(r + 8) * LDS_ + kb + tig];
                uint32_t aB2 = sBm[r * LDS_ + kb + tig + 4];
                uint32_t aB3 = sBm[(r + 8) * LDS_ + kb + tig + 4];
                #pragma unroll
                for (int ni = 0; ni < 4; ni++) {
                    mma_tf32(cU[mi][ni], aA0, aA1, aA2, aA3, bfu[ni][0], bfu[ni][1]);
                    mma_tf32(cI[mi][ni], aB0, aB1, aB2, aB3, bfi[ni][0], bfi[ni][1]);
                }
            }
        }
        __syncthreads();
    }

    #pragma unroll
    for (int mi = 0; mi < 4; mi++) {
        int r0 = m0 + wm + mi * 16 + g;
        float d0 = g_Disc[r0], d1 = g_Disc[r0 + 8];
        #pragma unroll
        for (int ni = 0; ni < 4; ni++) {
            int col = n0 + wn + ni * 8 + tig * 2;
            float bu0 = bu[col], bu1 = bu[col + 1];
            float bi0 = bi[col], bi1 = bi[col + 1];
            float2 o0, o1;
            o0.x = (tanhf(cU[mi][ni][0] + bu0) - sigmoidf(cI[mi][ni][0] + bi0)) * d0;
            o0.y = (tanhf(cU[mi][ni][1] + bu1) - sigmoidf(cI[mi][ni][1] + bi1)) * d0;
            o1.x = (tanhf(cU[mi][ni][2] + bu0) - sigmoidf(cI[mi][ni][2] + bi0)) * d1;
            o1.y = (tanhf(cU[mi][ni][3] + bu1) - sigmoidf(cI[mi][ni][3] + bi1)) * d1;
            *(float2*)(g_X + (size_t)r0 * DH + col)       = o0;
            *(float2*)(g_X + (size_t)(r0 + 8) * DH + col) = o1;
        }
    }
}

// ---------------- K3: tf32-MMA GEMM, H = sigmoid(X@W1^T + b1) ----------------
__global__ void __launch_bounds__(256) k_mlp1_mma(const float* __restrict__ W1,
                                                  const float* __restrict__ b1)
{
    extern __shared__ uint32_t smx[];
    uint32_t* sA = smx;
    uint32_t* sW = smx + 128 * LDS_;

    int t = threadIdx.x, lane = t & 31, warp = t >> 5;
    int wm = (warp & 1) * 64;
    int wn = (warp >> 1) * 32;
    int m0 = blockIdx.x * 128, n0 = blockIdx.y * 128;
    int g   = lane >> 2;
    int tig = lane & 3;

    float c_[4][4][4];
    #pragma unroll
    for (int mi = 0; mi < 4; mi++)
        #pragma unroll
        for (int ni = 0; ni < 4; ni++)
            #pragma unroll
            for (int q = 0; q < 4; q++) c_[mi][ni][q] = 0.f;

    for (int kt = 0; kt < DH; kt += 32) {
        #pragma unroll
        for (int i = 0; i < 4; i++) {
            int idx = t + i * 256;
            int r = idx >> 3, c = (idx & 7) * 4;
            float4 v;
            v = *(const float4*)(g_X + (size_t)(m0 + r) * DH + kt + c);
            sA[r * LDS_ + c] = f2tf(v.x); sA[r * LDS_ + c + 1] = f2tf(v.y);
            sA[r * LDS_ + c + 2] = f2tf(v.z); sA[r * LDS_ + c + 3] = f2tf(v.w);
            v = *(const float4*)(W1 + (size_t)(n0 + r) * DH + kt + c);
            sW[r * LDS_ + c] = f2tf(v.x); sW[r * LDS_ + c + 1] = f2tf(v.y);
            sW[r * LDS_ + c + 2] = f2tf(v.z); sW[r * LDS_ + c + 3] = f2tf(v.w);
        }
        __syncthreads();
        #pragma unroll
        for (int kk = 0; kk < 4; kk++) {
            int kb = kk * 8;
            uint32_t bf[4][2];
            #pragma unroll
            for (int ni = 0; ni < 4; ni++) {
                int n = wn + ni * 8 + g;
                bf[ni][0] = sW[n * LDS_ + kb + tig];
                bf[ni][1] = sW[n * LDS_ + kb + tig + 4];
            }
            #pragma unroll
            for (int mi = 0; mi < 4; mi++) {
                int r = wm + mi * 16 + g;
                uint32_t a0 = sA[r * LDS_ + kb + tig];
                uint32_t a1 = sA[(r + 8) * LDS_ + kb + tig];
                uint32_t a2 = sA[r * LDS_ + kb + tig + 4];
                uint32_t a3 = sA[(r + 8) * LDS_ + kb + tig + 4];
                #pragma unroll
                for (int ni = 0; ni < 4; ni++)
                    mma_tf32(c_[mi][ni], a0, a1, a2, a3, bf[ni][0], bf[ni][1]);
            }
        }
        __syncthreads();
    }

    #pragma unroll
    for (int mi = 0; mi < 4; mi++) {
        int r0 = m0 + wm + mi * 16 + g;
        #pragma unroll
        for (int ni = 0; ni < 4; ni++) {
            int col = n0 + wn + ni * 8 + tig * 2;
            float b0 = b1[col], b1v = b1[col + 1];
            float2 o0, o1;
            o0.x = sigmoidf(c_[mi][ni][0] + b0);
            o0.y = sigmoidf(c_[mi][ni][1] + b1v);
            o1.x = sigmoidf(c_[mi][ni][2] + b0);
            o1.y = sigmoidf(c_[mi][ni][3] + b1v);
            *(float2*)(g_H + (size_t)r0 * H2 + col)       = o0;
            *(float2*)(g_H + (size_t)(r0 + 8) * H2 + col) = o1;
        }
    }
}

// ---------------- K4: final GEMV + sigmoid ----------------
__global__ void k_out(const float* __restrict__ W2, const float* __restrict__ b2,
                      float* __restrict__ out)
{
    int gw   = (blockIdx.x * blockDim.x + threadIdx.x) >> 5;
    int lane = threadIdx.x & 31;
    if (gw >= BATCH) return;
    const float4* h4 = (const float4*)(g_H + (size_t)gw * H2);
    const float4* w4 = (const float4*)W2;
    float s = 0.f;
    #pragma unroll
    for (int i = 0; i < 2; i++) {
        float4 hv = h4[lane + i * 32], wv = w4[lane + i * 32];
        s += hv.x * wv.x + hv.y * wv.y + hv.z * wv.z + hv.w * wv.w;
    }
    #pragma unroll
    for (int o = 16; o; o >>= 1) s += __shfl_xor_sync(0xffffffffu, s, o);
    if (lane == 0) out[gw] = sigmoidf(s + b2[0]);
}

// ---------------- host: numpy-legacy MT19937 graph reconstruction ----------------
namespace {
struct MT { uint32_t mt[624]; int idx; };
static void mt_seed(MT& s, uint32_t seed) {
    s.mt[0] = seed;
    for (int i = 1; i < 624; i++)
        s.mt[i] = 1812433253u * (s.mt[i-1] ^ (s.mt[i-1] >> 30)) + (uint32_t)i;
    s.idx = 624;
}
static uint32_t mt_next(MT& s) {
    if (s.idx >= 624) {
        for (int i = 0; i < 624; i++) {
            uint32_t y = (s.mt[i] & 0x80000000u) | (s.mt[(i+1) % 624] & 0x7fffffffu);
            s.mt[i] = s.mt[(i+397) % 624] ^ (y >> 1) ^ ((y & 1u) ? 0x9908b0dfu : 0u);
        }
        s.idx = 0;
    }
    uint32_t y = s.mt[s.idx++];
    y ^= y >> 11;
    y ^= (y << 7)  & 0x9d2c5680u;
    y ^= (y << 15) & 0xefc60000u;
    y ^= y >> 18;
    return y;
}
static uint32_t draw_bounded(MT& s, uint32_t rng) {
    uint32_t mask = rng; mask |= mask >> 1; mask |= mask >> 2; mask |= mask >> 4;
    mask |= mask >> 8; mask |= mask >> 16;
    uint32_t v;
    do { v = mt_next(s) & mask; } while (v > rng);
    return v;
}
static void build_graph(GraphP& gp, EdgeExp& ee, int& E) {
    MT mt; mt_seed(mt, 0u);
    int off = 0;
    for (int k = 0; k < NC; k++) {
        int l = 0;
        if (k > 0) {
            int hi = (k < 3 ? k : 3) + 1;
            l = (int)draw_bounded(mt, (uint32_t)(hi - 1));
        }
        int preds[3] = {0, 0, 0};
        if (l > 0) {
            int arr[NC];
            for (int i = 0; i < k; i++) arr[i] = i;
            for (int i = k - 1; i >= 1; i--) {
                uint32_t j = draw_bounded(mt, (uint32_t)i);
                int tmp = arr[i]; arr[i] = arr[(int)j]; arr[(int)j] = tmp;
            }
            for (int jj = 0; jj < l; jj++) preds[jj] = arr[jj];
            for (int a = 0; a < l; a++)
                for (int b2_ = a + 1; b2_ < l; b2_++)
                    if (preds[b2_] < preds[a]) { int tm = preds[a]; preds[a] = preds[b2_]; preds[b2_] = tm; }
        }
        gp.lp[k] = (unsigned char)l;
        for (int jj = 0; jj < 3; jj++) gp.pred[k][jj] = (unsigned char)(jj < l ? preds[jj] : 0);
        for (int jj = 0; jj < l; jj++) ee.lp[off + jj] = (unsigned char)l;
        off += l;
    }
    E = off;
}
} // namespace

extern "C" void kernel_launch(void* const* d_in, const int* in_sizes, int n_in,
                              void* d_out, int out_size)
{
    GraphP gp; EdgeExp ee; int E;
    build_graph(gp, ee, E);

    const int*   uid    = (const int*)  d_in[0];
    const int*   qid    = (const int*)  d_in[1];
    const float* priori = (const float*)d_in[2];
    const float* cpd    = (const float*)d_in[3];
    const float* cnd    = (const float*)d_in[4];
    const float* idiff  = (const float*)d_in[5];
    const float* idisc  = (const float*)d_in[6];
    const float* qt     = (const float*)d_in[7];
    const float* Wu     = (const float*)d_in[8];
    const float* bu     = (const float*)d_in[9];
    const float* Wi     = (const float*)d_in[10];
    const float* bi     = (const float*)d_in[11];
    const float* W1     = (const float*)d_in[12];
    const float* b1     = (const float*)d_in[13];
    const float* W2     = (const float*)d_in[14];
    const float* b2     = (const float*)d_in[15];
    float* out = (float*)d_out;

    int Ein = in_sizes[3] / NUM_USER;
    if (Ein > 0 && Ein <= MAXE) E = Ein;

    const int SM_FACTOR = 4 * 128 * LDS_ * 4;  // 73728 B
    const int SM_MLP1   = 2 * 128 * LDS_ * 4;  // 36864 B
    static bool attr_done = false;
    if (!attr_done) {
        cudaFuncSetAttribute(k_factor_mma, cudaFuncAttributeMaxDynamicSharedMemorySize, SM_FACTOR);
        cudaFuncSetAttribute(k_mlp1_mma,   cudaFuncAttributeMaxDynamicSharedMemorySize, SM_MLP1);
        attr_done = true;
    }

    int total = 2 * NC + 2 * E + 1;
    dim3 g0((total + 255) / 256, BATCH);
    k_elem<<<g0, 256>>>(uid, qid, priori, cpd, cnd, idiff, idisc, qt, ee, E);

    k_mastery<<<(BATCH + 127) / 128, 128>>>(qid, qt, gp, E);

    k_factor_mma<<<dim3(BATCH / 128, DH / 128), 256, SM_FACTOR>>>(Wu, bu, Wi, bi);

    k_mlp1_mma<<<dim3(BATCH / 128, H2 / 128), 256, SM_MLP1>>>(W1, b1);

    k_out<<<(BATCH * 32 + 255) / 256, 256>>>(W2, b2, out);
}